// round 9
// baseline (speedup 1.0000x reference)
#include <cuda_runtime.h>
#include <stdint.h>

// out[b,i,j,:] = pe[clamp(128 + j - i, 0, 256), :]
// B=4, S=512, D=128, pe is [512,128] fp32 (rows 0..256 referenced).
//
// HBM-write-bound: 537 MB irreducible stores, measured floor ~7.3 TB/s
// (~91% of HBM3e spec). Exhaustively verified alternatives: diagonal reuse
// (77.9us), batch-fold (76.3), TMA bulk stores (96.4), L2-residency split
// (74.5), 256-bit stores (107.0) -- DRAM-active pins at ~80% for every
// contiguous STG.128 variant regardless of issue mechanism.
//
// This variant: one warp per TWO consecutive output rows (1 KB contiguous).
// Keeps the optimal fully-contiguous warp->address ordering while halving
// warp count / index overhead and giving 2 independent STG.128 in flight.
// Rows j and j+1 for the same i (j0 even), so both rels are computed from
// one base. Grid exactly covers 524,288 warps -> no bounds check.

__global__ __launch_bounds__(256) void relpos_kernel2(
    const float4* __restrict__ pe,   // [512][32] float4
    float4* __restrict__ out)        // [B*S*S][32] float4
{
    unsigned gtid = blockIdx.x * 256u + threadIdx.x;
    unsigned pair = gtid >> 5;       // row-pair index (2 rows each)
    unsigned lane = gtid & 31;

    unsigned row0 = pair << 1;       // even row; j0 even -> same i for both
    int j0 = row0 & 511;
    int i  = (row0 >> 9) & 511;

    int rel0 = 128 + j0 - i;
    int rel1 = rel0 + 1;
    rel0 = rel0 < 0 ? 0 : (rel0 > 256 ? 256 : rel0);
    rel1 = rel1 < 0 ? 0 : (rel1 > 256 ? 256 : rel1);

    // two L1-resident 512B row reads, two contiguous 512B row writes
    float4 v0 = __ldg(pe + rel0 * 32 + lane);
    float4 v1 = __ldg(pe + rel1 * 32 + lane);

    float4* dst = out + (size_t)pair * 64 + lane;
    __stcs(dst,      v0);
    __stcs(dst + 32, v1);
}

extern "C" void kernel_launch(void* const* d_in, const int* in_sizes, int n_in,
                              void* d_out, int out_size)
{
    // d_in[0] = x (int32 [B,512], shape-only), d_in[1] = pe (float32 [512,128])
    const float4* pe = (const float4*)d_in[1];
    float4* out = (float4*)d_out;

    int n_rows = out_size >> 7;                 // B*S*S = 1,048,576
    int grid = (n_rows / 2 * 32) / 256;         // exact: 65,536

    relpos_kernel2<<<grid, 256>>>(pe, out);
}

// round 10
// speedup vs baseline: 1.0091x; 1.0091x over previous
#include <cuda_runtime.h>
#include <stdint.h>

// out[b,i,j,:] = pe[clamp(128 + j - i, 0, 256), :]
// B=4, S=512, D=128, pe is [512,128] fp32 (rows 0..256 referenced).
//
// HBM-write-bound: 537 MB irreducible stores. Contiguous STG.128 ordering
// is the measured-best family; rows-per-warp scan: 1 row -> DRAM 80.3%,
// 2 rows -> 82.1% (best). This variant: FOUR consecutive rows per warp
// (2 KB contiguous), 4 independent STG.128 in flight, index math amortized
// 4x. j0 % 4 == 0 so all 4 rows share one i; rels are rel0..rel0+3.
// Grid exactly covers 262,144 warps -> no bounds check.

__global__ __launch_bounds__(256) void relpos_kernel4(
    const float4* __restrict__ pe,   // [512][32] float4
    float4* __restrict__ out)        // [B*S*S][32] float4
{
    unsigned gtid = blockIdx.x * 256u + threadIdx.x;
    unsigned quad = gtid >> 5;       // 4-row group index
    unsigned lane = gtid & 31;

    unsigned row0 = quad << 2;       // j0 multiple of 4 -> same i for all 4
    int j0 = row0 & 511;
    int i  = (row0 >> 9) & 511;

    int rel = 128 + j0 - i;

    float4 v[4];
    #pragma unroll
    for (int t = 0; t < 4; ++t) {
        int r = rel + t;
        r = r < 0 ? 0 : (r > 256 ? 256 : r);
        v[t] = __ldg(pe + r * 32 + lane);   // L1-resident table
    }

    float4* dst = out + (size_t)quad * 128 + lane;
    #pragma unroll
    for (int t = 0; t < 4; ++t)
        __stcs(dst + t * 32, v[t]);         // 4 contiguous 512B row writes
}

extern "C" void kernel_launch(void* const* d_in, const int* in_sizes, int n_in,
                              void* d_out, int out_size)
{
    // d_in[0] = x (int32 [B,512], shape-only), d_in[1] = pe (float32 [512,128])
    const float4* pe = (const float4*)d_in[1];
    float4* out = (float4*)d_out;

    int n_rows = out_size >> 7;                 // B*S*S = 1,048,576
    int grid = (n_rows / 4 * 32) / 256;         // exact: 32,768

    relpos_kernel4<<<grid, 256>>>(pe, out);
}